// round 12
// baseline (speedup 1.0000x reference)
#include <cuda_runtime.h>
#include <cuda_fp16.h>
#include <cstdint>

#define B_      2048
#define ADIM    14
#define C_      128
#define H_      256
#define E_      182
#define NNODES  (B_*ADIM)   /* 28672 */
#define NROWS   (B_*E_)     /* 372736 */
#define NPAIR   (B_/2)      /* 1024 */

// ---------------- device scratch (no allocs allowed) ----------------
__device__ __align__(16) __half g_W2h [H_*H_];        // lin2_w fp16, row-major (g, h)
__device__ __align__(16) __half g_Wcat[512*C_];       // [W_left rows | W_right rows], k-contig
__device__ __align__(16) __half g_Xh  [NNODES*C_];    // x = g + state, fp16
__device__ __align__(16) __half g_Yh  [(size_t)NNODES*512]; // [yl(256,+b1) | yr(256)] fp16
__device__ __align__(16) float2 g_part[(size_t)NPAIR*384*4]; // (pm,ps) per (pair,row,ngroup4)

// ---------------- mma / barrier helpers ----------------
__device__ __forceinline__ void ldsm_x4(unsigned &r0,unsigned &r1,unsigned &r2,unsigned &r3, unsigned a){
  asm volatile("ldmatrix.sync.aligned.m8n8.x4.shared.b16 {%0,%1,%2,%3},[%4];"
    :"=r"(r0),"=r"(r1),"=r"(r2),"=r"(r3):"r"(a));
}
__device__ __forceinline__ void ldsm_x2(unsigned &r0,unsigned &r1, unsigned a){
  asm volatile("ldmatrix.sync.aligned.m8n8.x2.shared.b16 {%0,%1},[%2];"
    :"=r"(r0),"=r"(r1):"r"(a));
}
__device__ __forceinline__ void mma16816(float c[4], const unsigned a[4], const unsigned b[2]){
  asm volatile("mma.sync.aligned.m16n8k16.row.col.f32.f16.f16.f32 "
    "{%0,%1,%2,%3},{%4,%5,%6,%7},{%8,%9},{%0,%1,%2,%3};"
    :"+f"(c[0]),"+f"(c[1]),"+f"(c[2]),"+f"(c[3])
    :"r"(a[0]),"r"(a[1]),"r"(a[2]),"r"(a[3]),"r"(b[0]),"r"(b[1]));
}
__device__ __forceinline__ void mma16816s(float c[4], const unsigned a[4], unsigned b0, unsigned b1){
  asm volatile("mma.sync.aligned.m16n8k16.row.col.f32.f16.f16.f32 "
    "{%0,%1,%2,%3},{%4,%5,%6,%7},{%8,%9},{%0,%1,%2,%3};"
    :"+f"(c[0]),"+f"(c[1]),"+f"(c[2]),"+f"(c[3])
    :"r"(a[0]),"r"(a[1]),"r"(a[2]),"r"(a[3]),"r"(b0),"r"(b1));
}
__device__ __forceinline__ void cp16(unsigned dst, const void* src){
  asm volatile("cp.async.cg.shared.global [%0], [%1], 16;" :: "r"(dst), "l"(src));
}
#define CP_COMMIT() asm volatile("cp.async.commit_group;" ::: "memory")
#define CP_WAIT0()  asm volatile("cp.async.wait_group 0;" ::: "memory")
#define BAR_SYNC(id, n)   asm volatile("bar.sync %0, %1;"   :: "r"(id), "r"(n) : "memory")
#define BAR_ARRIVE(id, n) asm volatile("bar.arrive %0, %1;" :: "r"(id), "r"(n) : "memory")

__device__ __forceinline__ float lky(float v){ return v > 0.f ? v : 0.01f*v; }
__device__ __forceinline__ float softplus_(float x){ return fmaxf(x,0.f) + log1pf(expf(-fabsf(x))); }

// ---------------- K0: weight conversion ----------------
__global__ void k_prep(const float* __restrict__ lin1_w, const float* __restrict__ lin2_w){
  int i = blockIdx.x*blockDim.x + threadIdx.x;   // 65536 threads
  if (i < H_*H_) g_W2h[i] = __float2half(lin2_w[i]);
  if (i < 512*C_){
    int o = i >> 7, c = i & 127;
    float v = (o < H_) ? lin1_w[o*(2*C_) + c] : lin1_w[(o-H_)*(2*C_) + C_ + c];
    g_Wcat[i] = __float2half(v);
  }
}

// ---------------- K1: s_bar -> g -> X (8 batches per block) ----------------
__global__ __launch_bounds__(256,1)
void k1_build(const float* __restrict__ state, const float* __restrict__ conv_w,
              const float* __restrict__ conv_b){
  extern __shared__ float sm1[];
  float* cw   = sm1;                 // 128 x 129
  float* sbar = cw + 128*129;        // 8 x 128
  float* gg   = sbar + 8*128;        // 8 x 128
  int tid = threadIdx.x;
  int b0  = blockIdx.x * 8;

  for (int i = tid; i < 128*128; i += 256){ int r = i>>7, c = i&127; cw[r*129+c] = conv_w[i]; }
  for (int idx = tid; idx < 8*128; idx += 256){
    int bb = idx >> 7, c = idx & 127;
    const float* sp = state + (size_t)(b0+bb)*ADIM*C_ + c;
    float s = 0.f;
    #pragma unroll
    for (int i = 0; i < ADIM; i++) s += sp[i*C_];
    sbar[idx] = s * (1.0f/14.0f);
  }
  __syncthreads();
  #pragma unroll
  for (int u = 0; u < 4; u++){
    int o = tid + u*256;
    int bb = o >> 7, h = o & 127;
    const float* sb = sbar + bb*128;
    const float* w  = cw + h*129;
    float acc = 0.f;
    #pragma unroll 8
    for (int c = 0; c < 128; c++) acc += sb[c]*w[c];
    gg[o] = fmaxf(acc + conv_b[h], 0.f);
  }
  __syncthreads();
  for (int idx = tid; idx < 8*ADIM*C_; idx += 256){
    int bb = idx / (ADIM*C_); int rem = idx - bb*(ADIM*C_);
    int c  = rem & 127;
    size_t node = (size_t)(b0+bb)*ADIM + (rem >> 7);
    g_Xh[node*C_ + c] = __float2half(gg[bb*128 + c] + state[node*C_ + c]);
  }
}

// ---------------- K2: Y = X @ Wcat^T, fp16 out, b1 folded ----------------
__global__ __launch_bounds__(256,1)
void k2_ygemm(const float* __restrict__ lin1_b){
  extern __shared__ __half sm2[];
  __half* As = sm2;             // 128 x 136
  __half* Bs = As + 128*136;    // 128 x 136
  int tid = threadIdx.x;
  int m0 = blockIdx.x * 128, n0 = blockIdx.y * 128;

  for (int idx = tid; idx < 128*16; idx += 256){
    int r = idx >> 4, c = idx & 15;
    *(uint4*)&As[r*136 + c*8] = *(const uint4*)&g_Xh [(size_t)(m0+r)*C_ + c*8];
    *(uint4*)&Bs[r*136 + c*8] = *(const uint4*)&g_Wcat[(size_t)(n0+r)*C_ + c*8];
  }
  __syncthreads();

  int lane = tid & 31, warp = tid >> 5, wm = warp >> 2, wn = warp & 3;
  unsigned abase = (unsigned)__cvta_generic_to_shared(As);
  unsigned bbase = (unsigned)__cvta_generic_to_shared(Bs);
  float acc[4][4][4];
  #pragma unroll
  for (int i=0;i<4;i++) for (int j=0;j<4;j++) for (int q=0;q<4;q++) acc[i][j][q]=0.f;

  int rA = (lane & 7) + ((lane >> 3) & 1) * 8;
  int cA = (lane >> 4) * 8;
  int l16 = lane & 15;
  int rB = l16 & 7;
  int cB = (l16 >> 3) * 8;

  #pragma unroll
  for (int kk = 0; kk < 8; kk++){
    int k0 = kk*16;
    unsigned a[4][4], b[4][2];
    #pragma unroll
    for (int mi = 0; mi < 4; mi++){
      int row = wm*64 + mi*16 + rA;
      ldsm_x4(a[mi][0],a[mi][1],a[mi][2],a[mi][3], abase + (row*136 + k0 + cA)*2);
    }
    #pragma unroll
    for (int ni = 0; ni < 4; ni++){
      int row = wn*32 + ni*8 + rB;
      ldsm_x2(b[ni][0],b[ni][1], bbase + (row*136 + k0 + cB)*2);
    }
    #pragma unroll
    for (int mi = 0; mi < 4; mi++)
      #pragma unroll
      for (int ni = 0; ni < 4; ni++)
        mma16816(acc[mi][ni], a[mi], b[ni]);
  }
  bool leftblk = (n0 < 256);
  #pragma unroll
  for (int ni = 0; ni < 4; ni++){
    int col = n0 + wn*32 + ni*8 + ((lane & 3) << 1);
    float a0 = leftblk ? __ldg(&lin1_b[col])   : 0.f;
    float a1 = leftblk ? __ldg(&lin1_b[col+1]) : 0.f;
    #pragma unroll
    for (int mi = 0; mi < 4; mi++){
      int row = m0 + wm*64 + mi*16 + (lane >> 2);
      *(__half2*)&g_Yh[(size_t)row*512 + col] =
        __floats2half2_rn(acc[mi][ni][0] + a0, acc[mi][ni][1] + a1);
      *(__half2*)&g_Yh[(size_t)(row+8)*512 + col] =
        __floats2half2_rn(acc[mi][ni][2] + a0, acc[mi][ni][3] + a1);
    }
  }
}

// ---------------- K3: warp-specialized GEMM, 4 big GEMM warps ----------------
// 256 threads: warps 0-3 = GEMM (warp tile m64 x n64, grid 1m x 4n, chunk M=64),
// warps 4-7 = builders (H1 double-buffered) + Ys prefetch.
// Named barriers: ready0=1, ready1=2 (builders arrive, GEMM syncs);
//                 free0=3,  free1=4  (GEMM arrives, builders sync). Count=256.
//                 id 5 = builder-only barrier (count 128) guarding Ys lifetime.
__global__ __launch_bounds__(256,1)
void k3_main(const float* __restrict__ lin2_b,
             const float* __restrict__ mu_w, const float* __restrict__ sig_w){
  extern __shared__ __half sm3[];
  __half* Ys  = sm3;                 // 2 x 14 x 512 = 14336 halves (one pair)
  __half* W2s = Ys + 14336;          // 256 x 264 = 67584
  __half* H1a = W2s + 67584;         // 64 x 264
  __half* H1b = H1a + 16896;         // 64 x 264
  // total (14336 + 67584 + 2*16896)*2 = 231424 B

  int tid  = threadIdx.x;
  int lane = tid & 31, warp = tid >> 5;          // 8 warps
  bool isg = (warp < 4);
  int warp_n = warp & 3;

  // one-time: W2 into smem (stride 264)
  for (int idx = tid; idx < 256*32; idx += 256){
    int r = idx >> 5, c = idx & 31;
    *(uint4*)&W2s[r*264 + c*8] = ((const uint4*)g_W2h)[r*32 + c];
  }
  // per-thread head constants (GEMM warps; 8 n8-groups over n64)
  __half2 b2c[8], muc[8], sgc[8];
  if (isg){
    #pragma unroll
    for (int ni = 0; ni < 8; ni++){
      int col = warp_n*64 + ni*8 + ((lane & 3) << 1);
      b2c[ni] = __floats2half2_rn(__ldg(&lin2_b[col]), __ldg(&lin2_b[col+1]));
      muc[ni] = __floats2half2_rn(__ldg(&mu_w[col]),   __ldg(&mu_w[col+1]));
      sgc[ni] = __floats2half2_rn(__ldg(&sig_w[col]),  __ldg(&sig_w[col+1]));
    }
  }

  unsigned h1bs[2] = { (unsigned)__cvta_generic_to_shared(H1a),
                       (unsigned)__cvta_generic_to_shared(H1b) };
  unsigned ysb = (unsigned)__cvta_generic_to_shared(Ys);
  unsigned w2b = (unsigned)__cvta_generic_to_shared(W2s);
  int rA  = (lane & 7) + ((lane >> 3) & 1) * 8;  // A ldsm.x4 row
  int cA  = (lane >> 4) * 8;                      // A ldsm.x4 col
  int rB4 = lane & 15;                            // B ldsm.x4 row (n16 block)
  int cB4 = (lane >> 4) * 8;                      // B ldsm.x4 col

  const __half2 zero2 = __float2half2_rn(0.f);
  const __half2 s01   = __float2half2_rn(0.01f);

  int pstep = gridDim.x;
  int bt = tid & 127;   // builder-local index

  // initial Ys prefetch (builders only)
  if (!isg && blockIdx.x < NPAIR){
    const __half* src = g_Yh + (size_t)(blockIdx.x*2)*ADIM*512;
    for (int g = bt; g < 1792; g += 128) cp16(ysb + g*16, src + g*8);
    CP_COMMIT();
  }
  __syncthreads();   // W2s visible to all

  if (isg){
    // ================= GEMM role =================
    for (int pair = blockIdx.x; pair < NPAIR; pair += pstep){
      #pragma unroll 1
      for (int t = 0; t < 6; t++){
        int buf = t & 1;
        BAR_SYNC(1 + buf, 256);              // H1[buf] ready
        unsigned h1b = h1bs[buf];

        float acc[4][8][4];
        #pragma unroll
        for (int i=0;i<4;i++) for (int j=0;j<8;j++) for (int q=0;q<4;q++) acc[i][j][q]=0.f;

        unsigned a[2][4][4], bq[2][4][4];
        // prologue: fragments for kk=0
        #pragma unroll
        for (int mi = 0; mi < 4; mi++){
          int row = mi*16 + rA;
          ldsm_x4(a[0][mi][0],a[0][mi][1],a[0][mi][2],a[0][mi][3], h1b + (row*264 + cA)*2);
        }
        #pragma unroll
        for (int nj = 0; nj < 4; nj++){
          int row = warp_n*64 + nj*16 + rB4;
          ldsm_x4(bq[0][nj][0],bq[0][nj][1],bq[0][nj][2],bq[0][nj][3], w2b + (row*264 + cB4)*2);
        }
        #pragma unroll
        for (int kk = 0; kk < 16; kk++){
          int cb = kk & 1, nb = cb ^ 1;
          if (kk < 15){
            int k1 = (kk+1)*16;
            #pragma unroll
            for (int mi = 0; mi < 4; mi++){
              int row = mi*16 + rA;
              ldsm_x4(a[nb][mi][0],a[nb][mi][1],a[nb][mi][2],a[nb][mi][3],
                      h1b + (row*264 + k1 + cA)*2);
            }
            #pragma unroll
            for (int nj = 0; nj < 4; nj++){
              int row = warp_n*64 + nj*16 + rB4;
              ldsm_x4(bq[nb][nj][0],bq[nb][nj][1],bq[nb][nj][2],bq[nb][nj][3],
                      w2b + (row*264 + k1 + cB4)*2);
            }
          }
          // bq regs: r0 = n0-7/k0-7, r1 = n8-15/k0-7, r2 = n0-7/k8-15, r3 = n8-15/k8-15
          #pragma unroll
          for (int mi = 0; mi < 4; mi++)
            #pragma unroll
            for (int nj = 0; nj < 4; nj++){
              mma16816s(acc[mi][2*nj],   a[cb][mi], bq[cb][nj][0], bq[cb][nj][2]);
              mma16816s(acc[mi][2*nj+1], a[cb][mi], bq[cb][nj][1], bq[cb][nj][3]);
            }
        }
        BAR_ARRIVE(3 + buf, 256);            // H1[buf] free (epilogue doesn't read it)

        // ---- epilogue: +b2, leaky, mu/sig dots, shfl-reduce, STG partials ----
        float2* pbase = g_part + ((size_t)pair*384 + t*64)*4 + warp_n;
        #pragma unroll
        for (int mi = 0; mi < 4; mi++){
          float pm0=0.f, ps0=0.f, pm1=0.f, ps1=0.f;
          #pragma unroll
          for (int ni = 0; ni < 8; ni++){
            float2 bb = __half22float2(b2c[ni]);
            float2 mm = __half22float2(muc[ni]);
            float2 ss = __half22float2(sgc[ni]);
            float v0 = lky(acc[mi][ni][0] + bb.x);
            float v1 = lky(acc[mi][ni][1] + bb.y);
            float v2 = lky(acc[mi][ni][2] + bb.x);
            float v3 = lky(acc[mi][ni][3] + bb.y);
            pm0 += v0*mm.x + v1*mm.y;
            ps0 += v0*ss.x + v1*ss.y;
            pm1 += v2*mm.x + v3*mm.y;
            ps1 += v2*ss.x + v3*ss.y;
          }
          pm0 += __shfl_xor_sync(0xffffffffu, pm0, 1); pm0 += __shfl_xor_sync(0xffffffffu, pm0, 2);
          ps0 += __shfl_xor_sync(0xffffffffu, ps0, 1); ps0 += __shfl_xor_sync(0xffffffffu, ps0, 2);
          pm1 += __shfl_xor_sync(0xffffffffu, pm1, 1); pm1 += __shfl_xor_sync(0xffffffffu, pm1, 2);
          ps1 += __shfl_xor_sync(0xffffffffu, ps1, 1); ps1 += __shfl_xor_sync(0xffffffffu, ps1, 2);
          if ((lane & 3) == 0){
            int row = mi*16 + (lane >> 2);
            pbase[(size_t)row*4]     = make_float2(pm0, ps0);
            pbase[(size_t)(row+8)*4] = make_float2(pm1, ps1);
          }
        }
      }
    }
  } else {
    // ================= builder role =================
    int gc = 0;
    for (int pair = blockIdx.x; pair < NPAIR; pair += pstep){
      CP_WAIT0();                          // own cp.async groups done
      BAR_SYNC(5, 128);                    // ALL builders' Ys writes visible
      #pragma unroll 1
      for (int t = 0; t < 6; t++){
        int buf = t & 1;
        if (gc >= 2) BAR_SYNC(3 + buf, 256);   // wait GEMM done with H1[buf]
        __half* H1d = buf ? H1b : H1a;
        #pragma unroll
        for (int it = 0; it < 16; it++){
          int idx = bt + it*128;           // 64*32 entries
          int m  = idx >> 5;
          int c8 = idx & 31;
          int rg = t*64 + m;               // 0..383
          int bsel = (rg >= 192) ? 1 : 0;
          int e = rg - 192*bsel;
          uint4 val;
          if (e < E_){
            int ii = e/13; int r = e - ii*13; int jj = r + (r >= ii ? 1 : 0);
            uint4 ul = *(const uint4*)&Ys[(bsel*ADIM + ii)*512 + c8*8];
            uint4 ur = *(const uint4*)&Ys[(bsel*ADIM + jj)*512 + 256 + c8*8];
            const __half2* l2 = (const __half2*)&ul;
            const __half2* r2 = (const __half2*)&ur;
            __half2 o[4];
            #pragma unroll
            for (int q = 0; q < 4; q++){
              __half2 s = __hadd2(l2[q], r2[q]);
              o[q] = __hadd2(__hmax2(s, zero2), __hmul2(s01, __hmin2(s, zero2)));
            }
            val = *(uint4*)o;
          } else {
            val = make_uint4(0u,0u,0u,0u);
          }
          *(uint4*)&H1d[m*264 + c8*8] = val;
        }
        BAR_ARRIVE(1 + buf, 256);          // H1[buf] ready
        gc++;
      }
      BAR_SYNC(5, 128);                    // all builders done READING Ys
      // Ys dead: prefetch next pair
      int pn = pair + pstep;
      if (pn < NPAIR){
        const __half* src = g_Yh + (size_t)(pn*2)*ADIM*512;
        for (int g = bt; g < 1792; g += 128) cp16(ysb + g*16, src + g*8);
      }
      CP_COMMIT();
    }
  }
}

// ---------------- K4: heads + log-prob from partials ----------------
__global__ __launch_bounds__(192,1)
void k4_heads(const float* __restrict__ mu_b, const float* __restrict__ sig_b,
              const float* __restrict__ noise, float* __restrict__ out){
  __shared__ float wsum[6];
  int b = blockIdx.x;                 // 0..2047
  int tid = threadIdx.x;              // 0..191
  int pair = b >> 1, half = b & 1;
  const float2* src = g_part + ((size_t)pair*384 + half*192 + tid)*4;
  float mp = mu_b[0], sp = sig_b[0];
  #pragma unroll
  for (int q = 0; q < 4; q++){ float2 v = src[q]; mp += v.x; sp += v.y; }
  float c = 0.f;
  if (tid < E_){
    float mu = softplus_(mp);
    float sd = softplus_(sp);
    float nz = noise[(size_t)b*E_ + tid];
    out[(size_t)b*E_ + tid] = mu + sd*nz;
    c = -0.5f*nz*nz - logf(sd);
  }
  c += __shfl_xor_sync(0xffffffffu, c, 1);
  c += __shfl_xor_sync(0xffffffffu, c, 2);
  c += __shfl_xor_sync(0xffffffffu, c, 4);
  c += __shfl_xor_sync(0xffffffffu, c, 8);
  c += __shfl_xor_sync(0xffffffffu, c, 16);
  if ((tid & 31) == 0) wsum[tid >> 5] = c;
  __syncthreads();
  if (tid == 0){
    float s = wsum[0] + wsum[1] + wsum[2] + wsum[3] + wsum[4] + wsum[5];
    out[(size_t)NROWS + b] = s - (float)E_ * 0.91893853320467274f;
  }
}

// ---------------- host launcher ----------------
extern "C" void kernel_launch(void* const* d_in, const int* in_sizes, int n_in,
                              void* d_out, int out_size){
  const float* state  = (const float*)d_in[0];
  const float* conv_w = (const float*)d_in[1];
  const float* conv_b = (const float*)d_in[2];
  const float* lin1_w = (const float*)d_in[3];
  const float* lin1_b = (const float*)d_in[4];
  const float* lin2_w = (const float*)d_in[5];
  const float* lin2_b = (const float*)d_in[6];
  const float* mu_w   = (const float*)d_in[7];
  const float* mu_b   = (const float*)d_in[8];
  const float* sig_w  = (const float*)d_in[9];
  const float* sig_b  = (const float*)d_in[10];
  const float* noise  = (const float*)d_in[11];
  float* out = (float*)d_out;

  const int SM1 = (128*129 + 8*128 + 8*128) * 4;           // 74240
  const int SM2 = 2 * 128*136 * 2;                         // 69632
  const int SM3 = (14336 + 256*264 + 2*64*264) * 2;        // 231424

  cudaFuncSetAttribute(k1_build, cudaFuncAttributeMaxDynamicSharedMemorySize, SM1);
  cudaFuncSetAttribute(k2_ygemm, cudaFuncAttributeMaxDynamicSharedMemorySize, SM2);
  cudaFuncSetAttribute(k3_main,  cudaFuncAttributeMaxDynamicSharedMemorySize, SM3);

  k_prep<<<256, 256>>>(lin1_w, lin2_w);
  k1_build<<<256, 256, SM1>>>(state, conv_w, conv_b);
  k2_ygemm<<<dim3(224, 4), 256, SM2>>>(lin1_b);
  k3_main<<<152, 256, SM3>>>(lin2_b, mu_w, sig_w);
  k4_heads<<<B_, 192>>>(mu_b, sig_b, noise, out);
}